// round 2
// baseline (speedup 1.0000x reference)
#include <cuda_runtime.h>

// NCC: per-(b,c) 21x21 normalized cross-correlation.
//   inputs  (16,3,512,512) fp32   -> d_in[0] (larger)
//   template(16,3,21,21)   fp32   -> d_in[1]
//   out     (16,3,492,492) fp32
//
// Strategy:
//   Pass 0: z-normalize each template plane, emit even/odd-parity packed
//           weight pair tables (f32x2) so the main loop needs NO pack ops.
//   Pass 1: tiled direct correlation using fma.rn.f32x2 (sm_10x packed FFMA2,
//           2x fp32 rate), fused local-std epilogue via separable box sums
//           computed from the same smem tile.

#define EPSF    1e-8f
#define TH      21
#define PLANES  48
#define H       512
#define W       512
#define OH      492
#define OW      492
#define NPAIR   11           // 21 taps -> 11 packed pairs (zero padded)
#define TILE_X  128
#define TILE_Y  16
#define SROWS   (TILE_Y + 20)   // 36
#define SCOLS   (TILE_X + 20)   // 148
#define NTHREADS 256

typedef unsigned long long ull;

// packed weight tables: [plane][filter_row i][pair t]
__device__ ull g_wE[PLANES * TH * NPAIR];
__device__ ull g_wO[PLANES * TH * NPAIR];

__device__ __forceinline__ ull pack2(float a, float b) {
    ull r; asm("mov.b64 %0, {%1,%2};" : "=l"(r) : "f"(a), "f"(b)); return r;
}
__device__ __forceinline__ float lo2(ull v) { return __int_as_float((int)(v & 0xffffffffull)); }
__device__ __forceinline__ float hi2(ull v) { return __int_as_float((int)(v >> 32)); }

// packed fp32x2 FMA: acc.lo += a.lo*b.lo ; acc.hi += a.hi*b.hi
#define FMA2(acc, a, b) asm("fma.rn.f32x2 %0, %1, %2, %0;" : "+l"(acc) : "l"(a), "l"(b))

// ---------------------------------------------------------------------------
// Pass 0: normalize template planes, build packed even/odd weight tables.
//   nt[j] = (t[j]-mean)/((std+EPS)*441)
//   wE[t] = (nt[2t],   nt[2t+1])   (nt[21]=0)
//   wO[t] = (nt[2t-1], nt[2t]  )   (nt[-1]=0)
// ---------------------------------------------------------------------------
__global__ void prep_template(const float* __restrict__ tmpl) {
    const int plane = blockIdx.x;
    const float* t = tmpl + plane * (TH * TH);

    __shared__ float s_t[TH * TH];
    __shared__ float s_sa[8], s_sb[8];
    __shared__ float s_mean, s_inv;

    int tid = threadIdx.x;
    float a = 0.f, b = 0.f;
    for (int i = tid; i < TH * TH; i += NTHREADS) {
        float v = t[i];
        s_t[i] = v;
        a += v; b += v * v;
    }
    #pragma unroll
    for (int o = 16; o; o >>= 1) {
        a += __shfl_xor_sync(0xffffffffu, a, o);
        b += __shfl_xor_sync(0xffffffffu, b, o);
    }
    if ((tid & 31) == 0) { s_sa[tid >> 5] = a; s_sb[tid >> 5] = b; }
    __syncthreads();
    if (tid == 0) {
        float sum = 0.f, sq = 0.f;
        #pragma unroll
        for (int wdx = 0; wdx < 8; wdx++) { sum += s_sa[wdx]; sq += s_sb[wdx]; }
        float mean = sum * (1.f / 441.f);
        float var  = fmaxf(sq * (1.f / 441.f) - mean * mean, 0.f);
        float stdv = sqrtf(var);
        s_mean = mean;
        s_inv  = 1.f / ((stdv + EPSF) * 441.f);
    }
    __syncthreads();

    const float mean = s_mean, inv = s_inv;
    for (int idx = tid; idx < TH * NPAIR; idx += NTHREADS) {
        int i  = idx / NPAIR;
        int tt = idx % NPAIR;
        int j0 = 2 * tt;
        float e0 = (s_t[i * TH + j0] - mean) * inv;                         // j0 <= 20 always
        float e1 = (j0 + 1 < TH) ? (s_t[i * TH + j0 + 1] - mean) * inv : 0.f;
        float o0 = (j0 - 1 >= 0) ? (s_t[i * TH + j0 - 1] - mean) * inv : 0.f;
        g_wE[plane * TH * NPAIR + idx] = pack2(e0, e1);
        g_wO[plane * TH * NPAIR + idx] = pack2(o0, e0);
    }
}

// ---------------------------------------------------------------------------
// Pass 1: main NCC kernel. One block = 128x16 output tile of one plane.
// 256 threads, each computes 8 consecutive-x outputs of one row.
// ---------------------------------------------------------------------------
__global__ __launch_bounds__(NTHREADS)
void ncc_main(const float* __restrict__ inp, float* __restrict__ out) {
    __shared__ __align__(16) float s_in[SROWS][SCOLS];   // 21.3 KB
    __shared__ ull   s_wE[TH][NPAIR];                    // 1.85 KB
    __shared__ ull   s_wO[TH][NPAIR];                    // 1.85 KB
    __shared__ float s_v1[TILE_Y][SCOLS];                // 9.5 KB
    __shared__ float s_v2[TILE_Y][SCOLS];                // 9.5 KB

    const int plane = blockIdx.z;
    const int x0 = blockIdx.x * TILE_X;
    const int y0 = blockIdx.y * TILE_Y;
    const int tid = threadIdx.x;

    const float* pin = inp + (size_t)plane * (H * W);

    // Load input tile (zero-fill out of bounds; 512 is 4-aligned so float4
    // groups are either fully in or fully out of range).
    for (int g = tid; g < SROWS * (SCOLS / 4); g += NTHREADS) {
        int r = g / (SCOLS / 4);
        int c = (g % (SCOLS / 4)) * 4;
        int gy = y0 + r, gx = x0 + c;
        float4 v = make_float4(0.f, 0.f, 0.f, 0.f);
        if (gy < H && gx < W) v = *(const float4*)(pin + (size_t)gy * W + gx);
        *(float4*)&s_in[r][c] = v;
    }
    // Load packed weights.
    for (int idx = tid; idx < TH * NPAIR; idx += NTHREADS) {
        ((ull*)s_wE)[idx] = g_wE[plane * TH * NPAIR + idx];
        ((ull*)s_wO)[idx] = g_wO[plane * TH * NPAIR + idx];
    }
    __syncthreads();

    const int ty = tid >> 4;          // output row within tile (0..15)
    const int xb = (tid & 15) * 8;    // output col base within tile

    ull acc[8];
    #pragma unroll
    for (int m = 0; m < 8; m++) acc[m] = 0ull;

    // Main correlation loop: 21 filter rows x 11 packed taps x 8 outputs.
    for (int i = 0; i < TH; i++) {
        const float* row = &s_in[ty + i][xb];
        ull p[14];
        #pragma unroll
        for (int u = 0; u < 7; u++) {
            ulonglong2 q = *(const ulonglong2*)(row + 4 * u);   // LDS.128
            p[2 * u]     = q.x;
            p[2 * u + 1] = q.y;
        }
        #pragma unroll
        for (int t = 0; t < NPAIR; t++) {
            ull we = s_wE[i][t];
            ull wo = s_wO[i][t];
            #pragma unroll
            for (int a4 = 0; a4 < 4; a4++) {
                FMA2(acc[2 * a4],     p[a4 + t], we);   // even-based output
                FMA2(acc[2 * a4 + 1], p[a4 + t], wo);   // odd-based output
            }
        }
    }

    // Vertical sliding box sums of x and x^2 over 21 rows (threads 0..147).
    if (tid < SCOLS) {
        const int c = tid;
        float s1 = 0.f, s2 = 0.f;
        #pragma unroll
        for (int r = 0; r < TH; r++) { float v = s_in[r][c]; s1 += v; s2 += v * v; }
        s_v1[0][c] = s1; s_v2[0][c] = s2;
        for (int y = 1; y < TILE_Y; y++) {
            float va = s_in[y + 20][c], vr = s_in[y - 1][c];
            s1 += va - vr;
            s2 += va * va - vr * vr;
            s_v1[y][c] = s1; s_v2[y][c] = s2;
        }
    }
    __syncthreads();

    // Horizontal sliding box sums + normalize + store.
    const float inv441 = 1.f / 441.f;
    float h1 = 0.f, h2 = 0.f;
    #pragma unroll
    for (int k = 0; k < TH; k++) { h1 += s_v1[ty][xb + k]; h2 += s_v2[ty][xb + k]; }

    const int oy = y0 + ty;
    float* pout = out + (size_t)plane * (OH * OW);
    #pragma unroll
    for (int m = 0; m < 8; m++) {
        if (m > 0) {
            h1 += s_v1[ty][xb + m + 20] - s_v1[ty][xb + m - 1];
            h2 += s_v2[ty][xb + m + 20] - s_v2[ty][xb + m - 1];
        }
        int ox = x0 + xb + m;
        if (oy < OH && ox < OW) {
            float mean = h1 * inv441;
            float msq  = h2 * inv441;
            float stdv = sqrtf(msq - mean * mean + EPSF);
            float num  = lo2(acc[m]) + hi2(acc[m]);
            pout[(size_t)oy * OW + ox] = num / (stdv + EPSF);
        }
    }
}

extern "C" void kernel_launch(void* const* d_in, const int* in_sizes, int n_in,
                              void* d_out, int out_size) {
    const float* inp  = (const float*)d_in[0];
    const float* tmpl = (const float*)d_in[1];
    if (n_in >= 2 && in_sizes[0] < in_sizes[1]) {   // defensive ordering
        const float* t = inp; inp = tmpl; tmpl = t;
    }
    prep_template<<<PLANES, NTHREADS>>>(tmpl);
    dim3 grid((OW + TILE_X - 1) / TILE_X,   // 4
              (OH + TILE_Y - 1) / TILE_Y,   // 31
              PLANES);                      // 48
    ncc_main<<<grid, NTHREADS>>>(inp, (float*)d_out);
}

// round 3
// speedup vs baseline: 1.1328x; 1.1328x over previous
#include <cuda_runtime.h>

// NCC: per-(b,c) 21x21 normalized cross-correlation.
//   inputs  (16,3,512,512) fp32, template (16,3,21,21) fp32 -> out (16,3,492,492) fp32
//
// R3: LDS-wavefront reduction.
//   - wE/wO interleaved into one ulonglong2 table -> 1 broadcast LDS.128/(row,pair)
//   - 2 output rows per thread (TILE_Y=32): weight loads amortized 2x
//   - dynamic smem (72 KB) since static limit is 48 KB

#define EPSF    1e-8f
#define TH      21
#define PLANES  48
#define H       512
#define W       512
#define OH      492
#define OW      492
#define NPAIR   11
#define TILE_X  128
#define TILE_Y  32
#define SROWS   (TILE_Y + 20)   // 52
#define SCOLS   (TILE_X + 20)   // 148
#define NTHREADS 256

typedef unsigned long long ull;

// interleaved packed weight table: [plane][filter_row i][pair t] = (wE, wO)
__device__ ulonglong2 g_wEO[PLANES * TH * NPAIR];

__device__ __forceinline__ ull pack2(float a, float b) {
    ull r; asm("mov.b64 %0, {%1,%2};" : "=l"(r) : "f"(a), "f"(b)); return r;
}
__device__ __forceinline__ float lo2(ull v) { return __int_as_float((int)(v & 0xffffffffull)); }
__device__ __forceinline__ float hi2(ull v) { return __int_as_float((int)(v >> 32)); }

#define FMA2(acc, a, b) asm("fma.rn.f32x2 %0, %1, %2, %0;" : "+l"(acc) : "l"(a), "l"(b))

// smem layout (bytes)
#define OFF_W    0
#define SZ_W     (TH * NPAIR * 16)                 // 3696
#define OFF_IN   (OFF_W + SZ_W)                    // 3696 (16-aligned)
#define SZ_IN    (SROWS * SCOLS * 4)               // 30784
#define OFF_V1   (OFF_IN + SZ_IN)                  // 34480
#define SZ_V     (TILE_Y * SCOLS * 4)              // 18944
#define OFF_V2   (OFF_V1 + SZ_V)                   // 53424
#define SMEM_TOTAL (OFF_V2 + SZ_V)                 // 72368

// ---------------------------------------------------------------------------
// Pass 0: normalize template planes, build interleaved packed weight table.
// ---------------------------------------------------------------------------
__global__ void prep_template(const float* __restrict__ tmpl) {
    const int plane = blockIdx.x;
    const float* t = tmpl + plane * (TH * TH);

    __shared__ float s_t[TH * TH];
    __shared__ float s_sa[8], s_sb[8];
    __shared__ float s_mean, s_inv;

    int tid = threadIdx.x;
    float a = 0.f, b = 0.f;
    for (int i = tid; i < TH * TH; i += NTHREADS) {
        float v = t[i];
        s_t[i] = v;
        a += v; b += v * v;
    }
    #pragma unroll
    for (int o = 16; o; o >>= 1) {
        a += __shfl_xor_sync(0xffffffffu, a, o);
        b += __shfl_xor_sync(0xffffffffu, b, o);
    }
    if ((tid & 31) == 0) { s_sa[tid >> 5] = a; s_sb[tid >> 5] = b; }
    __syncthreads();
    if (tid == 0) {
        float sum = 0.f, sq = 0.f;
        #pragma unroll
        for (int wdx = 0; wdx < 8; wdx++) { sum += s_sa[wdx]; sq += s_sb[wdx]; }
        float mean = sum * (1.f / 441.f);
        float var  = fmaxf(sq * (1.f / 441.f) - mean * mean, 0.f);
        s_mean = mean;
        s_inv  = 1.f / ((sqrtf(var) + EPSF) * 441.f);
    }
    __syncthreads();

    const float mean = s_mean, inv = s_inv;
    for (int idx = tid; idx < TH * NPAIR; idx += NTHREADS) {
        int i  = idx / NPAIR;
        int tt = idx % NPAIR;
        int j0 = 2 * tt;
        float e0 = (s_t[i * TH + j0] - mean) * inv;
        float e1 = (j0 + 1 < TH) ? (s_t[i * TH + j0 + 1] - mean) * inv : 0.f;
        float o0 = (j0 - 1 >= 0) ? (s_t[i * TH + j0 - 1] - mean) * inv : 0.f;
        ulonglong2 w;
        w.x = pack2(e0, e1);   // even-based-output weights
        w.y = pack2(o0, e0);   // odd-based-output weights
        g_wEO[plane * TH * NPAIR + idx] = w;
    }
}

// ---------------------------------------------------------------------------
// Pass 1: main NCC. Block = 128x32 output tile. 256 threads, each thread
// computes 2 output rows x 8 consecutive columns.
// ---------------------------------------------------------------------------
__global__ __launch_bounds__(NTHREADS, 2)
void ncc_main(const float* __restrict__ inp, float* __restrict__ out) {
    extern __shared__ __align__(16) char dynsmem[];
    ulonglong2* s_wEO          = (ulonglong2*)(dynsmem + OFF_W);   // [TH][NPAIR]
    float (*s_in)[SCOLS]       = (float(*)[SCOLS])(dynsmem + OFF_IN);
    float (*s_v1)[SCOLS]       = (float(*)[SCOLS])(dynsmem + OFF_V1);
    float (*s_v2)[SCOLS]       = (float(*)[SCOLS])(dynsmem + OFF_V2);

    const int plane = blockIdx.z;
    const int x0 = blockIdx.x * TILE_X;
    const int y0 = blockIdx.y * TILE_Y;
    const int tid = threadIdx.x;

    const float* pin = inp + (size_t)plane * (H * W);

    // Load input tile (zero-fill OOB; W=512 keeps float4 groups aligned).
    for (int g = tid; g < SROWS * (SCOLS / 4); g += NTHREADS) {
        int r = g / (SCOLS / 4);
        int c = (g % (SCOLS / 4)) * 4;
        int gy = y0 + r, gx = x0 + c;
        float4 v = make_float4(0.f, 0.f, 0.f, 0.f);
        if (gy < H && gx < W) v = *(const float4*)(pin + (size_t)gy * W + gx);
        *(float4*)&s_in[r][c] = v;
    }
    for (int idx = tid; idx < TH * NPAIR; idx += NTHREADS)
        s_wEO[idx] = g_wEO[plane * TH * NPAIR + idx];
    __syncthreads();

    const int ty2 = tid >> 4;          // 0..15
    const int yb  = ty2 * 2;           // first of 2 output rows
    const int xb  = (tid & 15) * 8;    // output col base

    ull accA[8], accB[8];
    #pragma unroll
    for (int m = 0; m < 8; m++) { accA[m] = 0ull; accB[m] = 0ull; }

    // 21 filter rows; each iteration serves both output rows from one set of
    // broadcast weight loads.
    for (int i = 0; i < TH; i++) {
        const float* rA = &s_in[yb + i][xb];
        const float* rB = rA + SCOLS;
        ull pA[14], pB[14];
        #pragma unroll
        for (int u = 0; u < 7; u++) {
            ulonglong2 qa = *(const ulonglong2*)(rA + 4 * u);
            pA[2 * u] = qa.x; pA[2 * u + 1] = qa.y;
            ulonglong2 qb = *(const ulonglong2*)(rB + 4 * u);
            pB[2 * u] = qb.x; pB[2 * u + 1] = qb.y;
        }
        #pragma unroll
        for (int t = 0; t < NPAIR; t++) {
            ulonglong2 w = s_wEO[i * NPAIR + t];    // one broadcast LDS.128
            #pragma unroll
            for (int a4 = 0; a4 < 4; a4++) {
                FMA2(accA[2 * a4],     pA[a4 + t], w.x);
                FMA2(accA[2 * a4 + 1], pA[a4 + t], w.y);
                FMA2(accB[2 * a4],     pB[a4 + t], w.x);
                FMA2(accB[2 * a4 + 1], pB[a4 + t], w.y);
            }
        }
    }

    // Vertical sliding box sums over 21 rows (threads 0..147, one column each).
    if (tid < SCOLS) {
        const int c = tid;
        float s1 = 0.f, s2 = 0.f;
        #pragma unroll
        for (int r = 0; r < TH; r++) { float v = s_in[r][c]; s1 += v; s2 += v * v; }
        s_v1[0][c] = s1; s_v2[0][c] = s2;
        for (int y = 1; y < TILE_Y; y++) {
            float va = s_in[y + 20][c], vr = s_in[y - 1][c];
            s1 += va - vr;
            s2 += va * va - vr * vr;
            s_v1[y][c] = s1; s_v2[y][c] = s2;
        }
    }
    __syncthreads();

    // Horizontal sliding sums + normalize + store, for both output rows.
    const float inv441 = 1.f / 441.f;
    float* pout = out + (size_t)plane * (OH * OW);

    #pragma unroll
    for (int rr = 0; rr < 2; rr++) {
        const int yrow = yb + rr;
        const ull* acc = rr ? accB : accA;
        float h1 = 0.f, h2 = 0.f;
        #pragma unroll
        for (int k = 0; k < TH; k++) { h1 += s_v1[yrow][xb + k]; h2 += s_v2[yrow][xb + k]; }
        const int oy = y0 + yrow;
        #pragma unroll
        for (int m = 0; m < 8; m++) {
            if (m > 0) {
                h1 += s_v1[yrow][xb + m + 20] - s_v1[yrow][xb + m - 1];
                h2 += s_v2[yrow][xb + m + 20] - s_v2[yrow][xb + m - 1];
            }
            int ox = x0 + xb + m;
            if (oy < OH && ox < OW) {
                float mean = h1 * inv441;
                float msq  = h2 * inv441;
                float stdv = sqrtf(msq - mean * mean + EPSF);
                float num  = lo2(acc[m]) + hi2(acc[m]);
                pout[(size_t)oy * OW + ox] = num / (stdv + EPSF);
            }
        }
    }
}

extern "C" void kernel_launch(void* const* d_in, const int* in_sizes, int n_in,
                              void* d_out, int out_size) {
    const float* inp  = (const float*)d_in[0];
    const float* tmpl = (const float*)d_in[1];
    if (n_in >= 2 && in_sizes[0] < in_sizes[1]) {
        const float* t = inp; inp = tmpl; tmpl = t;
    }
    cudaFuncSetAttribute(ncc_main, cudaFuncAttributeMaxDynamicSharedMemorySize,
                         SMEM_TOTAL);
    prep_template<<<PLANES, NTHREADS>>>(tmpl);
    dim3 grid((OW + TILE_X - 1) / TILE_X,   // 4
              (OH + TILE_Y - 1) / TILE_Y,   // 16
              PLANES);                      // 48
    ncc_main<<<grid, NTHREADS, SMEM_TOTAL>>>(inp, (float*)d_out);
}

// round 4
// speedup vs baseline: 1.2072x; 1.0657x over previous
#include <cuda_runtime.h>

// NCC: per-(b,c) 21x21 normalized cross-correlation, fp32.
// R4: 16 outputs/thread in x (fewer pixel loads per FMA2), XOR bank swizzle on
// the smem tile (pixel LDS.128 at the 4-phase minimum), register-resident
// horizontal box-sum epilogue. Target: FMA2-pipe bound.

#define EPSF    1e-8f
#define TH      21
#define PLANES  48
#define H       512
#define W       512
#define OH      492
#define OW      492
#define NPAIR   11
#define TILE_X  128          // 8 x-threads * 16 outputs
#define TILE_Y  32           // 32 y-threads * 1 row
#define SROWS   (TILE_Y + 20)     // 52
#define NCHUNK  37                // 148 floats = 37 16B-chunks (logical)
#define ROWCH   40                // padded physical chunks per row
#define ROWB    (ROWCH * 16)      // 640 B row stride
#define NTHREADS 256

typedef unsigned long long ull;

// interleaved packed weight table: [plane][filter_row][pair] = (wE, wO)
__device__ ulonglong2 g_wEO[PLANES * TH * NPAIR];

__device__ __forceinline__ ull pack2(float a, float b) {
    ull r; asm("mov.b64 %0, {%1,%2};" : "=l"(r) : "f"(a), "f"(b)); return r;
}
__device__ __forceinline__ float lo2(ull v) { return __int_as_float((int)(v & 0xffffffffull)); }
__device__ __forceinline__ float hi2(ull v) { return __int_as_float((int)(v >> 32)); }

#define FMA2(acc, a, b) asm("fma.rn.f32x2 %0, %1, %2, %0;" : "+l"(acc) : "l"(a), "l"(b))

// XOR swizzle on 16B-chunk index (keeps chunks inside their 128B segment)
__device__ __forceinline__ int swz(int c) { return c ^ ((c >> 3) & 7); }

// smem layout (bytes)
#define OFF_W    0
#define SZ_W     (TH * NPAIR * 16)            // 3696
#define OFF_IN   3712                          // 16B aligned
#define SZ_IN    (SROWS * ROWB)                // 33280
#define OFF_V1   (OFF_IN + SZ_IN)              // 36992
#define SZ_V     (TILE_Y * ROWB)               // 20480
#define OFF_V2   (OFF_V1 + SZ_V)               // 57472
#define SMEM_TOTAL (OFF_V2 + SZ_V)             // 77952

// ---------------------------------------------------------------------------
// Pass 0: normalize template planes, build interleaved packed weight table.
// ---------------------------------------------------------------------------
__global__ void prep_template(const float* __restrict__ tmpl) {
    const int plane = blockIdx.x;
    const float* t = tmpl + plane * (TH * TH);

    __shared__ float s_t[TH * TH];
    __shared__ float s_sa[8], s_sb[8];
    __shared__ float s_mean, s_inv;

    int tid = threadIdx.x;
    float a = 0.f, b = 0.f;
    for (int i = tid; i < TH * TH; i += NTHREADS) {
        float v = t[i];
        s_t[i] = v;
        a += v; b += v * v;
    }
    #pragma unroll
    for (int o = 16; o; o >>= 1) {
        a += __shfl_xor_sync(0xffffffffu, a, o);
        b += __shfl_xor_sync(0xffffffffu, b, o);
    }
    if ((tid & 31) == 0) { s_sa[tid >> 5] = a; s_sb[tid >> 5] = b; }
    __syncthreads();
    if (tid == 0) {
        float sum = 0.f, sq = 0.f;
        #pragma unroll
        for (int wdx = 0; wdx < 8; wdx++) { sum += s_sa[wdx]; sq += s_sb[wdx]; }
        float mean = sum * (1.f / 441.f);
        float var  = fmaxf(sq * (1.f / 441.f) - mean * mean, 0.f);
        s_mean = mean;
        s_inv  = 1.f / ((sqrtf(var) + EPSF) * 441.f);
    }
    __syncthreads();

    const float mean = s_mean, inv = s_inv;
    for (int idx = tid; idx < TH * NPAIR; idx += NTHREADS) {
        int i  = idx / NPAIR;
        int tt = idx % NPAIR;
        int j0 = 2 * tt;
        float e0 = (s_t[i * TH + j0] - mean) * inv;
        float e1 = (j0 + 1 < TH) ? (s_t[i * TH + j0 + 1] - mean) * inv : 0.f;
        float o0 = (j0 - 1 >= 0) ? (s_t[i * TH + j0 - 1] - mean) * inv : 0.f;
        ulonglong2 w;
        w.x = pack2(e0, e1);   // even-based outputs
        w.y = pack2(o0, e0);   // odd-based outputs
        g_wEO[plane * TH * NPAIR + idx] = w;
    }
}

// ---------------------------------------------------------------------------
// Pass 1: main NCC. Block = 128x32 tile; thread = 1 row x 16 consecutive cols.
// ---------------------------------------------------------------------------
__global__ __launch_bounds__(NTHREADS, 2)
void ncc_main(const float* __restrict__ inp, float* __restrict__ out) {
    extern __shared__ __align__(16) char dynsmem[];
    ulonglong2* s_wEO = (ulonglong2*)(dynsmem + OFF_W);
    char* s_in  = dynsmem + OFF_IN;
    char* s_v1  = dynsmem + OFF_V1;
    char* s_v2  = dynsmem + OFF_V2;

    const int plane = blockIdx.z;
    const int x0 = blockIdx.x * TILE_X;
    const int y0 = blockIdx.y * TILE_Y;
    const int tid = threadIdx.x;

    const float* pin = inp + (size_t)plane * (H * W);

    // Load input tile: 52 rows x 37 logical chunks, swizzled placement.
    for (int g = tid; g < SROWS * NCHUNK; g += NTHREADS) {
        int r = g / NCHUNK;
        int c = g - r * NCHUNK;              // logical 16B chunk
        int gy = y0 + r, gx = x0 + 4 * c;
        float4 v = make_float4(0.f, 0.f, 0.f, 0.f);
        if (gy < H && gx < W) v = *(const float4*)(pin + (size_t)gy * W + gx);
        *(float4*)(s_in + r * ROWB + swz(c) * 16) = v;
    }
    for (int idx = tid; idx < TH * NPAIR; idx += NTHREADS)
        s_wEO[idx] = g_wEO[plane * TH * NPAIR + idx];
    __syncthreads();

    const int xt = tid & 7;        // 16-output column group
    const int yt = tid >> 3;       // output row within tile

    // Precomputed swizzled byte offsets for this thread's 9 pixel chunks.
    int coff[9];
    #pragma unroll
    for (int u = 0; u < 9; u++) coff[u] = swz(4 * xt + u) * 16;

    ull acc[16];
    #pragma unroll
    for (int m = 0; m < 16; m++) acc[m] = 0ull;

    const char* srow = s_in + yt * ROWB;
    #pragma unroll 1
    for (int i = 0; i < TH; i++) {
        ulonglong2 w[NPAIR];
        #pragma unroll
        for (int t = 0; t < NPAIR; t++) w[t] = s_wEO[i * NPAIR + t];  // broadcast

        ull p[18];
        #pragma unroll
        for (int u = 0; u < 9; u++) {
            ulonglong2 q = *(const ulonglong2*)(srow + coff[u]);      // 4-phase LDS.128
            p[2 * u] = q.x; p[2 * u + 1] = q.y;
        }
        #pragma unroll
        for (int t = 0; t < NPAIR; t++) {
            #pragma unroll
            for (int g = 0; g < 8; g++) {
                FMA2(acc[2 * g],     p[g + t], w[t].x);
                FMA2(acc[2 * g + 1], p[g + t], w[t].y);
            }
        }
        srow += ROWB;
    }

    // Vertical sliding box sums of x, x^2 (threads 0..147, one column each),
    // written swizzled so the epilogue can vector-load them.
    if (tid < 148) {
        const int c = tid;
        const int colb = swz(c >> 2) * 16 + (c & 3) * 4;   // swizzled byte off in row
        float s1 = 0.f, s2 = 0.f;
        #pragma unroll
        for (int r = 0; r < TH; r++) {
            float v = *(const float*)(s_in + r * ROWB + colb);
            s1 += v; s2 += v * v;
        }
        *(float*)(s_v1 + colb) = s1;
        *(float*)(s_v2 + colb) = s2;
        for (int y = 1; y < TILE_Y; y++) {
            float va = *(const float*)(s_in + (y + 20) * ROWB + colb);
            float vr = *(const float*)(s_in + (y - 1) * ROWB + colb);
            s1 += va - vr;
            s2 += va * va - vr * vr;
            *(float*)(s_v1 + y * ROWB + colb) = s1;
            *(float*)(s_v2 + y * ROWB + colb) = s2;
        }
    }
    __syncthreads();

    // Epilogue: reduce packed accumulators, register-resident horizontal sums.
    float num[16];
    #pragma unroll
    for (int m = 0; m < 16; m++) num[m] = lo2(acc[m]) + hi2(acc[m]);

    float h1[16], h2[16];
    {
        float V[36];
        #pragma unroll
        for (int u = 0; u < 9; u++) {
            float4 q = *(const float4*)(s_v1 + yt * ROWB + coff[u]);
            V[4*u] = q.x; V[4*u+1] = q.y; V[4*u+2] = q.z; V[4*u+3] = q.w;
        }
        float h = 0.f;
        #pragma unroll
        for (int k = 0; k < TH; k++) h += V[k];
        h1[0] = h;
        #pragma unroll
        for (int m = 1; m < 16; m++) { h += V[m + 20] - V[m - 1]; h1[m] = h; }
    }
    {
        float V[36];
        #pragma unroll
        for (int u = 0; u < 9; u++) {
            float4 q = *(const float4*)(s_v2 + yt * ROWB + coff[u]);
            V[4*u] = q.x; V[4*u+1] = q.y; V[4*u+2] = q.z; V[4*u+3] = q.w;
        }
        float h = 0.f;
        #pragma unroll
        for (int k = 0; k < TH; k++) h += V[k];
        h2[0] = h;
        #pragma unroll
        for (int m = 1; m < 16; m++) { h += V[m + 20] - V[m - 1]; h2[m] = h; }
    }

    const float inv441 = 1.f / 441.f;
    const int oy = y0 + yt;
    const int oxb = x0 + 16 * xt;
    if (oy < OH) {
        float* prow = out + (size_t)plane * (OH * OW) + (size_t)oy * OW;
        #pragma unroll
        for (int q4 = 0; q4 < 4; q4++) {
            int ox = oxb + 4 * q4;
            if (ox + 3 < OW) {                 // OW divisible by 4, ox 4-aligned
                float4 o;
                float* po = &o.x;
                #pragma unroll
                for (int e = 0; e < 4; e++) {
                    int m = 4 * q4 + e;
                    float mean = h1[m] * inv441;
                    float msq  = h2[m] * inv441;
                    float stdv = sqrtf(msq - mean * mean + EPSF);
                    po[e] = num[m] / (stdv + EPSF);
                }
                *(float4*)(prow + ox) = o;
            }
        }
    }
}

extern "C" void kernel_launch(void* const* d_in, const int* in_sizes, int n_in,
                              void* d_out, int out_size) {
    const float* inp  = (const float*)d_in[0];
    const float* tmpl = (const float*)d_in[1];
    if (n_in >= 2 && in_sizes[0] < in_sizes[1]) {
        const float* t = inp; inp = tmpl; tmpl = t;
    }
    cudaFuncSetAttribute(ncc_main, cudaFuncAttributeMaxDynamicSharedMemorySize,
                         SMEM_TOTAL);
    prep_template<<<PLANES, NTHREADS>>>(tmpl);
    dim3 grid((OW + TILE_X - 1) / TILE_X,   // 4
              (OH + TILE_Y - 1) / TILE_Y,   // 16
              PLANES);                      // 48
    ncc_main<<<grid, NTHREADS, SMEM_TOTAL>>>(inp, (float*)d_out);
}

// round 6
// speedup vs baseline: 1.2155x; 1.0069x over previous
#include <cuda_runtime.h>

// NCC: per-(b,c) 21x21 normalized cross-correlation, fp32.
// R6 = R4 (validated, 258us) + software-pipelined mainloop:
//   2-deep manual pipeline, unrolled x2 so ping/pong pixel buffers are pure
//   register renaming. Pixel LDS for row i+1 issue during row i's FMA block,
//   removing the long-scoreboard stall at the loop top (fma pipe was 41% idle).

#define EPSF    1e-8f
#define TH      21
#define PLANES  48
#define H       512
#define W       512
#define OH      492
#define OW      492
#define NPAIR   11
#define TILE_X  128          // 8 x-threads * 16 outputs
#define TILE_Y  32           // 32 y-threads * 1 row
#define SROWS   (TILE_Y + 20)     // 52
#define NCHUNK  37                // 148 floats = 37 16B-chunks (logical)
#define ROWCH   40                // padded physical chunks per row
#define ROWB    (ROWCH * 16)      // 640 B row stride
#define NTHREADS 256

typedef unsigned long long ull;

// interleaved packed weight table: [plane][filter_row][pair] = (wE, wO)
__device__ ulonglong2 g_wEO[PLANES * TH * NPAIR];

__device__ __forceinline__ ull pack2(float a, float b) {
    ull r; asm("mov.b64 %0, {%1,%2};" : "=l"(r) : "f"(a), "f"(b)); return r;
}
__device__ __forceinline__ float lo2(ull v) { return __int_as_float((int)(v & 0xffffffffull)); }
__device__ __forceinline__ float hi2(ull v) { return __int_as_float((int)(v >> 32)); }

#define FMA2(acc, a, b) asm("fma.rn.f32x2 %0, %1, %2, %0;" : "+l"(acc) : "l"(a), "l"(b))

// XOR swizzle on 16B-chunk index (keeps chunks inside their 128B segment)
__device__ __forceinline__ int swz(int c) { return c ^ ((c >> 3) & 7); }

// smem layout (bytes)
#define OFF_W    0
#define SZ_W     (TH * NPAIR * 16)            // 3696
#define OFF_IN   3712                          // 16B aligned
#define SZ_IN    (SROWS * ROWB)                // 33280
#define OFF_V1   (OFF_IN + SZ_IN)              // 36992
#define SZ_V     (TILE_Y * ROWB)               // 20480
#define OFF_V2   (OFF_V1 + SZ_V)               // 57472
#define SMEM_TOTAL (OFF_V2 + SZ_V)             // 77952

// ---------------------------------------------------------------------------
// Pass 0: normalize template planes, build interleaved packed weight table.
// ---------------------------------------------------------------------------
__global__ void prep_template(const float* __restrict__ tmpl) {
    const int plane = blockIdx.x;
    const float* t = tmpl + plane * (TH * TH);

    __shared__ float s_t[TH * TH];
    __shared__ float s_sa[8], s_sb[8];
    __shared__ float s_mean, s_inv;

    int tid = threadIdx.x;
    float a = 0.f, b = 0.f;
    for (int i = tid; i < TH * TH; i += NTHREADS) {
        float v = t[i];
        s_t[i] = v;
        a += v; b += v * v;
    }
    #pragma unroll
    for (int o = 16; o; o >>= 1) {
        a += __shfl_xor_sync(0xffffffffu, a, o);
        b += __shfl_xor_sync(0xffffffffu, b, o);
    }
    if ((tid & 31) == 0) { s_sa[tid >> 5] = a; s_sb[tid >> 5] = b; }
    __syncthreads();
    if (tid == 0) {
        float sum = 0.f, sq = 0.f;
        #pragma unroll
        for (int wdx = 0; wdx < 8; wdx++) { sum += s_sa[wdx]; sq += s_sb[wdx]; }
        float mean = sum * (1.f / 441.f);
        float var  = fmaxf(sq * (1.f / 441.f) - mean * mean, 0.f);
        s_mean = mean;
        s_inv  = 1.f / ((sqrtf(var) + EPSF) * 441.f);
    }
    __syncthreads();

    const float mean = s_mean, inv = s_inv;
    for (int idx = tid; idx < TH * NPAIR; idx += NTHREADS) {
        int i  = idx / NPAIR;
        int tt = idx % NPAIR;
        int j0 = 2 * tt;
        float e0 = (s_t[i * TH + j0] - mean) * inv;
        float e1 = (j0 + 1 < TH) ? (s_t[i * TH + j0 + 1] - mean) * inv : 0.f;
        float o0 = (j0 - 1 >= 0) ? (s_t[i * TH + j0 - 1] - mean) * inv : 0.f;
        ulonglong2 w;
        w.x = pack2(e0, e1);   // even-based outputs
        w.y = pack2(o0, e0);   // odd-based outputs
        g_wEO[plane * TH * NPAIR + idx] = w;
    }
}

// helper macros for the pipelined mainloop ----------------------------------
#define LOAD_PIX(buf, rowptr) do { \
    _Pragma("unroll") \
    for (int _u = 0; _u < 9; _u++) { \
        ulonglong2 _q = *(const ulonglong2*)((rowptr) + coff[_u]); \
        (buf)[2 * _u] = _q.x; (buf)[2 * _u + 1] = _q.y; \
    } \
} while (0)

#define LOAD_W(wbuf, i) do { \
    _Pragma("unroll") \
    for (int _t = 0; _t < NPAIR; _t++) (wbuf)[_t] = s_wEO[(i) * NPAIR + _t]; \
} while (0)

#define FMA_ROW(buf, wbuf) do { \
    _Pragma("unroll") \
    for (int _t = 0; _t < NPAIR; _t++) { \
        _Pragma("unroll") \
        for (int _g = 0; _g < 8; _g++) { \
            FMA2(acc[2 * _g],     (buf)[_g + _t], (wbuf)[_t].x); \
            FMA2(acc[2 * _g + 1], (buf)[_g + _t], (wbuf)[_t].y); \
        } \
    } \
} while (0)

// ---------------------------------------------------------------------------
// Pass 1: main NCC. Block = 128x32 tile; thread = 1 row x 16 consecutive cols.
// ---------------------------------------------------------------------------
__global__ __launch_bounds__(NTHREADS, 2)
void ncc_main(const float* __restrict__ inp, float* __restrict__ out) {
    extern __shared__ __align__(16) char dynsmem[];
    ulonglong2* s_wEO = (ulonglong2*)(dynsmem + OFF_W);
    char* s_in  = dynsmem + OFF_IN;
    char* s_v1  = dynsmem + OFF_V1;
    char* s_v2  = dynsmem + OFF_V2;

    const int plane = blockIdx.z;
    const int x0 = blockIdx.x * TILE_X;
    const int y0 = blockIdx.y * TILE_Y;
    const int tid = threadIdx.x;

    const float* pin = inp + (size_t)plane * (H * W);

    // Load input tile: 52 rows x 37 logical chunks, swizzled placement.
    for (int g = tid; g < SROWS * NCHUNK; g += NTHREADS) {
        int r = g / NCHUNK;
        int c = g - r * NCHUNK;              // logical 16B chunk
        int gy = y0 + r, gx = x0 + 4 * c;
        float4 v = make_float4(0.f, 0.f, 0.f, 0.f);
        if (gy < H && gx < W) v = *(const float4*)(pin + (size_t)gy * W + gx);
        *(float4*)(s_in + r * ROWB + swz(c) * 16) = v;
    }
    for (int idx = tid; idx < TH * NPAIR; idx += NTHREADS)
        s_wEO[idx] = g_wEO[plane * TH * NPAIR + idx];
    __syncthreads();

    const int xt = tid & 7;        // 16-output column group
    const int yt = tid >> 3;       // output row within tile

    // Precomputed swizzled byte offsets for this thread's 9 pixel chunks.
    int coff[9];
    #pragma unroll
    for (int u = 0; u < 9; u++) coff[u] = swz(4 * xt + u) * 16;

    ull acc[16];
    #pragma unroll
    for (int m = 0; m < 16; m++) acc[m] = 0ull;

    // ---- software-pipelined mainloop: 21 filter rows --------------------
    const char* base = s_in + yt * ROWB;
    ull p[18], q[18];
    ulonglong2 w[NPAIR];

    LOAD_PIX(p, base);                         // row 0
    #pragma unroll 1
    for (int i = 0; i < 20; i += 2) {
        LOAD_W(w, i);
        LOAD_PIX(q, base + (i + 1) * ROWB);    // prefetch row i+1
        FMA_ROW(p, w);                         // row i
        LOAD_W(w, i + 1);
        LOAD_PIX(p, base + (i + 2) * ROWB);    // prefetch row i+2 (<= 20)
        FMA_ROW(q, w);                         // row i+1
    }
    LOAD_W(w, 20);
    FMA_ROW(p, w);                             // row 20

    // Vertical sliding box sums of x, x^2 (threads 0..147, one column each),
    // written swizzled so the epilogue can vector-load them.
    if (tid < 148) {
        const int c = tid;
        const int colb = swz(c >> 2) * 16 + (c & 3) * 4;   // swizzled byte off in row
        float s1 = 0.f, s2 = 0.f;
        #pragma unroll
        for (int r = 0; r < TH; r++) {
            float v = *(const float*)(s_in + r * ROWB + colb);
            s1 += v; s2 += v * v;
        }
        *(float*)(s_v1 + colb) = s1;
        *(float*)(s_v2 + colb) = s2;
        for (int y = 1; y < TILE_Y; y++) {
            float va = *(const float*)(s_in + (y + 20) * ROWB + colb);
            float vr = *(const float*)(s_in + (y - 1) * ROWB + colb);
            s1 += va - vr;
            s2 += va * va - vr * vr;
            *(float*)(s_v1 + y * ROWB + colb) = s1;
            *(float*)(s_v2 + y * ROWB + colb) = s2;
        }
    }
    __syncthreads();

    // Epilogue: reduce packed accumulators, register-resident horizontal sums.
    float num[16];
    #pragma unroll
    for (int m = 0; m < 16; m++) num[m] = lo2(acc[m]) + hi2(acc[m]);

    float h1[16], h2[16];
    {
        float V[36];
        #pragma unroll
        for (int u = 0; u < 9; u++) {
            float4 qv = *(const float4*)(s_v1 + yt * ROWB + coff[u]);
            V[4*u] = qv.x; V[4*u+1] = qv.y; V[4*u+2] = qv.z; V[4*u+3] = qv.w;
        }
        float h = 0.f;
        #pragma unroll
        for (int k = 0; k < TH; k++) h += V[k];
        h1[0] = h;
        #pragma unroll
        for (int m = 1; m < 16; m++) { h += V[m + 20] - V[m - 1]; h1[m] = h; }
    }
    {
        float V[36];
        #pragma unroll
        for (int u = 0; u < 9; u++) {
            float4 qv = *(const float4*)(s_v2 + yt * ROWB + coff[u]);
            V[4*u] = qv.x; V[4*u+1] = qv.y; V[4*u+2] = qv.z; V[4*u+3] = qv.w;
        }
        float h = 0.f;
        #pragma unroll
        for (int k = 0; k < TH; k++) h += V[k];
        h2[0] = h;
        #pragma unroll
        for (int m = 1; m < 16; m++) { h += V[m + 20] - V[m - 1]; h2[m] = h; }
    }

    const float inv441 = 1.f / 441.f;
    const int oy = y0 + yt;
    const int oxb = x0 + 16 * xt;
    if (oy < OH) {
        float* prow = out + (size_t)plane * (OH * OW) + (size_t)oy * OW;
        #pragma unroll
        for (int q4 = 0; q4 < 4; q4++) {
            int ox = oxb + 4 * q4;
            if (ox + 3 < OW) {                 // OW divisible by 4, ox 4-aligned
                float4 o;
                float* po = &o.x;
                #pragma unroll
                for (int e = 0; e < 4; e++) {
                    int m = 4 * q4 + e;
                    float mean = h1[m] * inv441;
                    float msq  = h2[m] * inv441;
                    float stdv = sqrtf(msq - mean * mean + EPSF);
                    po[e] = num[m] / (stdv + EPSF);
                }
                *(float4*)(prow + ox) = o;
            }
        }
    }
}

extern "C" void kernel_launch(void* const* d_in, const int* in_sizes, int n_in,
                              void* d_out, int out_size) {
    const float* inp  = (const float*)d_in[0];
    const float* tmpl = (const float*)d_in[1];
    if (n_in >= 2 && in_sizes[0] < in_sizes[1]) {
        const float* t = inp; inp = tmpl; tmpl = t;
    }
    cudaFuncSetAttribute(ncc_main, cudaFuncAttributeMaxDynamicSharedMemorySize,
                         SMEM_TOTAL);
    prep_template<<<PLANES, NTHREADS>>>(tmpl);
    dim3 grid((OW + TILE_X - 1) / TILE_X,   // 4
              (OH + TILE_Y - 1) / TILE_Y,   // 16
              PLANES);                      // 48
    ncc_main<<<grid, NTHREADS, SMEM_TOTAL>>>(inp, (float*)d_out);
}